// round 12
// baseline (speedup 1.0000x reference)
#include <cuda_runtime.h>
#include <cstdint>
#include <cstddef>

// ----------------------------------------------------------------------------
// Round 12: mbarrier cluster sync (no UCGABAR), G1a accumulates into hp_x
// (C1 combine 16->8 bufs), fast tanh via ex2/rcp approx.
//   a <- a + W2^T tanh([x_t; a] @ W1 + b1) + b2,  512 steps.
// 32 clusters x 4 CTAs; cluster owns 8 batch rows; CTA rank owns hidden slice
// [128r, 128r+128). G1 weights in registers (w1x[16]+w1a[16] ulonglong2).
//
// Per-step: G1a(acc into hp_x) | B2 | C1(8-buf + tanh_fast) | B3 | G2 | B4 |
//   C2(publish .cg) | B5 | tid0: fence+4x mbar arrive | G1x(t+1) rows 0-3 |
//   try_wait(parity) | fold ldcg x4 | G1x(t+1) rows 4-7 | fold+x-stage | B1
// ----------------------------------------------------------------------------

#define T_STEPS  512
#define DIN      128
#define DST      128
#define DHID     512
#define NCL      32
#define CSZ      4
#define ROWS     8
#define NTHREADS 256

typedef unsigned long long u64;

#define FMA2(acc, s, w) asm("fma.rn.f32x2 %0, %1, %2, %0;" : "+l"(acc) : "l"(s), "l"(w))
#define PACK2(d, v)     asm("mov.b64 %0, {%1, %1};"        : "=l"(d)   : "r"(__float_as_uint(v)))

// double-buffered per-rank partial states (1 MB static scratch)
__device__ float g_pstate[2][NCL][CSZ][ROWS][DST];

// smem layout (floats):
//   W2s  [128][128] @ 0      (64KB)
//   hp   [8][8][128]@ 16384  (32KB)  G2 partials
//   hp_x [8][8][128]@ 24576  (32KB)  G1x partials, then G1a-accumulated preacts
//   a_s  [8][128]   @ 32768  ( 4KB)
//   x2   [2][8][128]@ 33792  ( 8KB)
//   h_s  [8][128]   @ 35840  ( 4KB)
//   mbar (8B)       @ 36864
#define SMEM_FLOATS 36872    // 147488 B

static __device__ __forceinline__ float4 f4add(float4 a, float4 b) {
    return make_float4(a.x + b.x, a.y + b.y, a.z + b.z, a.w + b.w);
}

// tanh(x) = 1 - 2/(e^{2x}+1) via ex2.approx/rcp.approx. Abs err ~1e-7,
// saturates correctly at +-inf (ex2->inf => 1; ex2->0 => -1).
static __device__ __forceinline__ float tanh_fast(float v) {
    float e, r;
    asm("ex2.approx.f32 %0, %1;" : "=f"(e) : "f"(v * 2.8853900817779268f));
    asm("rcp.approx.f32 %0, %1;" : "=f"(r) : "f"(e + 1.0f));
    return fmaf(-2.0f, r, 1.0f);
}

// 16-k x 4-row x 4-col GEMM partial with register weights (fresh write).
static __device__ __forceinline__ void gemm16_rows(
    const float* __restrict__ act, const ulonglong2* __restrict__ w,
    float* __restrict__ outp, int rlo)
{
    ulonglong2 acc[4];
    #pragma unroll
    for (int r = 0; r < 4; ++r) { acc[r].x = 0ull; acc[r].y = 0ull; }
    #pragma unroll
    for (int kb = 0; kb < 4; ++kb) {
        float4 av[4];
        #pragma unroll
        for (int r = 0; r < 4; ++r)
            av[r] = *(const float4*)(act + (rlo + r) * 128 + kb * 4);
        #pragma unroll
        for (int kk = 0; kk < 4; ++kk) {
            const ulonglong2 ww = w[kb * 4 + kk];
            #pragma unroll
            for (int r = 0; r < 4; ++r) {
                float s = (kk == 0) ? av[r].x : (kk == 1) ? av[r].y
                        : (kk == 2) ? av[r].z : av[r].w;
                u64 sp; PACK2(sp, s);
                FMA2(acc[r].x, sp, ww.x);
                FMA2(acc[r].y, sp, ww.y);
            }
        }
    }
    #pragma unroll
    for (int r = 0; r < 4; ++r)
        *(ulonglong2*)(outp + (rlo + r) * 128) = acc[r];
}

// Same, but accumulates on top of the existing buffer contents.
static __device__ __forceinline__ void gemm16_rows_acc(
    const float* __restrict__ act, const ulonglong2* __restrict__ w,
    float* __restrict__ outp, int rlo)
{
    ulonglong2 acc[4];
    #pragma unroll
    for (int r = 0; r < 4; ++r)
        acc[r] = *(const ulonglong2*)(outp + (rlo + r) * 128);
    #pragma unroll
    for (int kb = 0; kb < 4; ++kb) {
        float4 av[4];
        #pragma unroll
        for (int r = 0; r < 4; ++r)
            av[r] = *(const float4*)(act + (rlo + r) * 128 + kb * 4);
        #pragma unroll
        for (int kk = 0; kk < 4; ++kk) {
            const ulonglong2 ww = w[kb * 4 + kk];
            #pragma unroll
            for (int r = 0; r < 4; ++r) {
                float s = (kk == 0) ? av[r].x : (kk == 1) ? av[r].y
                        : (kk == 2) ? av[r].z : av[r].w;
                u64 sp; PACK2(sp, s);
                FMA2(acc[r].x, sp, ww.x);
                FMA2(acc[r].y, sp, ww.y);
            }
        }
    }
    #pragma unroll
    for (int r = 0; r < 4; ++r)
        *(ulonglong2*)(outp + (rlo + r) * 128) = acc[r];
}

__global__ void __cluster_dims__(CSZ, 1, 1) __launch_bounds__(NTHREADS, 1)
rnn_kernel(const float* __restrict__ x,  const float* __restrict__ a0,
           const float* __restrict__ W1, const float* __restrict__ b1,
           const float* __restrict__ W2, const float* __restrict__ b2,
           float* __restrict__ out)
{
    extern __shared__ float sm[];
    float* W2s  = sm;
    float* hp   = sm + 16384;
    float* hp_x = sm + 24576;
    float* a_s  = sm + 32768;
    float* x2   = sm + 33792;   // [2][8][128]
    float* h_s  = sm + 35840;

    uint32_t smem_u32;
    asm("{ .reg .u64 t; cvta.to.shared.u64 t, %1; cvt.u32.u64 %0, t; }"
        : "=r"(smem_u32) : "l"(sm));
    const uint32_t mb = smem_u32 + 36864u * 4u;

    const int tid   = threadIdx.x;
    const int lane  = tid & 31;
    const int wid   = tid >> 5;
    const int bx    = blockIdx.x;
    const int crank = bx & (CSZ - 1);
    const int gcl   = bx >> 2;
    const int rowbase = gcl * ROWS;
    const int jbase   = crank * 128;
    const int cj      = lane * 4;

    // ---- G1 weights into registers ----
    ulonglong2 w1x[16], w1a[16];
    {
        const float* ws = W1 + (size_t)(16 * wid) * DHID + jbase + cj;
        #pragma unroll
        for (int r = 0; r < 16; ++r)
            w1x[r] = *(const ulonglong2*)(ws + (size_t)r * DHID);
        const float* wa = W1 + (size_t)(128 + 16 * wid) * DHID + jbase + cj;
        #pragma unroll
        for (int r = 0; r < 16; ++r)
            w1a[r] = *(const ulonglong2*)(wa + (size_t)r * DHID);
    }

    // ---- prologue: W2 slice, a0, x(0) ----
    for (int i = tid; i < 4096; i += NTHREADS)
        ((float4*)W2s)[i] = ((const float4*)(W2 + (size_t)jbase * DST))[i];
    for (int i = tid; i < 256; i += NTHREADS)
        ((float4*)a_s)[i] = ((const float4*)(a0 + (size_t)rowbase * DST))[i];
    for (int i = tid; i < 256; i += NTHREADS) {
        int r = i >> 5, c4 = (i & 31) << 2;
        *(float4*)(x2 + r * 128 + c4) =
            *(const float4*)(x + (size_t)(rowbase + r) * (size_t)(T_STEPS * DIN) + c4);
    }

    const int crow = wid;                 // this warp's batch row
    const float4 rb1 = *(const float4*)(b1 + jbase + cj);
    const float4 rb2 = *(const float4*)(b2 + cj);

    const float* xrow = x + (size_t)(rowbase + crow) * (size_t)(T_STEPS * DIN) + cj;
    *(float4*)(x2 + 1024 + crow * 128 + cj) = *(const float4*)(xrow + DIN);  // x(1)
    float4 xr = *(const float4*)(xrow + 2 * DIN);                            // x(2)

    const float* g2_wr = W2s + (wid * 16) * 128 + cj;
    float* hpo  = hp   + wid * 1024 + cj;
    float* hpxo = hp_x + wid * 1024 + cj;

    if (tid == 0)
        asm volatile("mbarrier.init.shared.b64 [%0], %1;" :: "r"(mb), "r"(4u) : "memory");
    __syncthreads();
    // cluster-wide: mbarriers initialized before any remote arrive
    asm volatile("barrier.cluster.arrive.aligned;" ::: "memory");
    asm volatile("barrier.cluster.wait.aligned;"   ::: "memory");

    // ---- G1x for step 0 ----
    gemm16_rows(x2 + wid * 16, w1x, hpxo, 0);
    gemm16_rows(x2 + wid * 16, w1x, hpxo, 4);
    __syncthreads();   // B1 (step 0 entry)

    for (int t = 0; t < T_STEPS; ++t) {
        // ---- G1a: accumulate a-part on top of G1x partials in hp_x ----
        gemm16_rows_acc(a_s + wid * 16, w1a, hpxo, 0);
        gemm16_rows_acc(a_s + wid * 16, w1a, hpxo, 4);
        __syncthreads();   // B2

        // ---- C1: preact = sum(8 hp_x bufs) + b1 -> tanh_fast -> h_s ----
        {
            const float* hbx = hp_x + crow * 128 + cj;
            float4 s = *(const float4*)(hbx);
            #pragma unroll
            for (int q = 1; q < 8; ++q)
                s = f4add(s, *(const float4*)(hbx + q * 1024));
            float4 hv;
            hv.x = tanh_fast(s.x + rb1.x);
            hv.y = tanh_fast(s.y + rb1.y);
            hv.z = tanh_fast(s.z + rb1.z);
            hv.w = tanh_fast(s.w + rb1.w);
            *(float4*)(h_s + crow * 128 + cj) = hv;
        }
        __syncthreads();   // B3

        // ---- G2: warp = 16-j chunk x 8 rows, smem weights ----
        {
            ulonglong2 acc[ROWS];
            #pragma unroll
            for (int r = 0; r < ROWS; ++r) { acc[r].x = 0ull; acc[r].y = 0ull; }
            const float* act2 = h_s + wid * 16;
            #pragma unroll
            for (int kb = 0; kb < 4; ++kb) {
                #pragma unroll
                for (int half = 0; half < 2; ++half) {
                    float4 av[4];
                    #pragma unroll
                    for (int r = 0; r < 4; ++r)
                        av[r] = *(const float4*)(act2 + (half * 4 + r) * 128 + kb * 4);
                    const float* wk = g2_wr + kb * 4 * 128;
                    #pragma unroll
                    for (int kk = 0; kk < 4; ++kk) {
                        const ulonglong2 ww = *(const ulonglong2*)(wk + kk * 128);
                        #pragma unroll
                        for (int r = 0; r < 4; ++r) {
                            float s = (kk == 0) ? av[r].x : (kk == 1) ? av[r].y
                                    : (kk == 2) ? av[r].z : av[r].w;
                            u64 sp; PACK2(sp, s);
                            FMA2(acc[half * 4 + r].x, sp, ww.x);
                            FMA2(acc[half * 4 + r].y, sp, ww.y);
                        }
                    }
                }
            }
            #pragma unroll
            for (int r = 0; r < ROWS; ++r)
                *(ulonglong2*)(hpo + r * 128) = acc[r];
        }
        __syncthreads();   // B4

        // ---- C2: combine 8 G2 bufs -> publish my rank's state partial ----
        {
            const float* hb = hp + crow * 128 + cj;
            float4 s = *(const float4*)(hb);
            #pragma unroll
            for (int q = 1; q < 8; ++q)
                s = f4add(s, *(const float4*)(hb + q * 1024));
            __stcg((float4*)&g_pstate[t & 1][gcl][crank][crow][cj], s);
        }
        __syncthreads();   // B5: all publish stores issued

        if (tid == 0) {
            asm volatile("fence.acq_rel.cluster;" ::: "memory");
            #pragma unroll
            for (int r = 0; r < CSZ; ++r) {
                asm volatile(
                    "{ .reg .b32 ra;\n\t"
                    "mapa.shared::cluster.u32 ra, %0, %1;\n\t"
                    "mbarrier.arrive.release.cluster.shared::cluster.b64 _, [ra]; }"
                    :: "r"(mb), "r"(r) : "memory");
            }
        }

        // ---- G1x(t+1) part A: rows 0-3, hides publish/arrive latency ----
        const float* xb = x2 + ((t + 1) & 1) * 1024 + wid * 16;
        if (t + 1 < T_STEPS)
            gemm16_rows(xb, w1x, hpxo, 0);

        // ---- wait for all 4 ranks' publishes (phase t, parity t&1) ----
        {
            const unsigned par = (unsigned)(t & 1);
            unsigned done = 0;
            while (!done) {
                asm volatile(
                    "{ .reg .pred p;\n\t"
                    "mbarrier.try_wait.parity.acquire.cluster.shared::cta.b64 p, [%1], %2, 0x989680;\n\t"
                    "selp.b32 %0, 1, 0, p; }"
                    : "=r"(done) : "r"(mb), "r"(par) : "memory");
            }
        }

        // ---- fold loads (L2), hidden under G1x part B ----
        float4 p0 = __ldcg((const float4*)&g_pstate[t & 1][gcl][0][crow][cj]);
        float4 p1 = __ldcg((const float4*)&g_pstate[t & 1][gcl][1][crow][cj]);
        float4 p2 = __ldcg((const float4*)&g_pstate[t & 1][gcl][2][crow][cj]);
        float4 p3 = __ldcg((const float4*)&g_pstate[t & 1][gcl][3][crow][cj]);

        if (t + 1 < T_STEPS)
            gemm16_rows(xb, w1x, hpxo, 4);

        // ---- fold combine: a(t+1) = a(t) + sum(partials) + b2 ----
        {
            float4 acc = f4add(f4add(p0, p1), f4add(p2, p3));
            float4 av = *(float4*)(a_s + crow * DST + cj);
            av.x += acc.x + rb2.x;  av.y += acc.y + rb2.y;
            av.z += acc.z + rb2.z;  av.w += acc.w + rb2.w;
            *(float4*)(a_s + crow * DST + cj) = av;
        }
        // ---- stage x(t+2); prefetch x(t+3) ----
        if (t + 2 < T_STEPS) {
            *(float4*)(x2 + (t & 1) * 1024 + crow * 128 + cj) = xr;
            if (t + 3 < T_STEPS)
                xr = *(const float4*)(xrow + (size_t)(t + 3) * DIN);
        }
        __syncthreads();   // B1
    }

    // ---- epilogue: a_s holds a(T); rank 0 writes out ----
    if (crank == 0) {
        float4 av = *(float4*)(a_s + crow * DST + cj);
        *(float4*)(out + (size_t)(rowbase + crow) * DST + cj) = av;
    }
}

extern "C" void kernel_launch(void* const* d_in, const int* in_sizes, int n_in,
                              void* d_out, int out_size) {
    const float* x  = (const float*)d_in[0];
    const float* a0 = (const float*)d_in[1];
    const float* W1 = (const float*)d_in[2];
    const float* b1 = (const float*)d_in[3];
    const float* W2 = (const float*)d_in[4];
    const float* b2 = (const float*)d_in[5];
    float* out = (float*)d_out;

    const size_t smem = SMEM_FLOATS * sizeof(float);   // 147488 B
    cudaFuncSetAttribute(rnn_kernel, cudaFuncAttributeMaxDynamicSharedMemorySize,
                         (int)smem);
    rnn_kernel<<<NCL * CSZ, NTHREADS, smem>>>(x, a0, W1, b1, W2, b2, out);
}

// round 13
// speedup vs baseline: 1.2466x; 1.2466x over previous
#include <cuda_runtime.h>
#include <cstdint>
#include <cstddef>

// ----------------------------------------------------------------------------
// Round 13 = Round 11 sync structure (barrier.cluster, proven 1769us)
//            + G1a-accumulate-into-hp_x (C1 combine 16->8)
//            + tanh_fast (ex2/rcp approx).
//   a <- a + W2^T tanh([x_t; a] @ W1 + b1) + b2,  512 steps.
// 32 clusters x 4 CTAs; cluster owns 8 batch rows; CTA rank owns hidden slice
// [128r, 128r+128). G1 weights in registers (w1x[16]+w1a[16] ulonglong2/thread).
//
// Per-step: G1a(acc into hp_x) | B2 | C1(8-buf + tanh_fast) | B3 | G2 | B4 |
//   C2(publish .cg) | cluster.arrive | G1x(t+1) rows 0-3 | cluster.wait |
//   fold ldcg x4 | G1x(t+1) rows 4-7 | fold combine + x stage | B1
// ----------------------------------------------------------------------------

#define T_STEPS  512
#define DIN      128
#define DST      128
#define DHID     512
#define NCL      32
#define CSZ      4
#define ROWS     8
#define NTHREADS 256

typedef unsigned long long u64;

#define FMA2(acc, s, w) asm("fma.rn.f32x2 %0, %1, %2, %0;" : "+l"(acc) : "l"(s), "l"(w))
#define PACK2(d, v)     asm("mov.b64 %0, {%1, %1};"        : "=l"(d)   : "r"(__float_as_uint(v)))

// double-buffered per-rank partial states (1 MB static scratch)
__device__ float g_pstate[2][NCL][CSZ][ROWS][DST];

// smem layout (floats):
//   W2s  [128][128] @ 0      (64KB)
//   hp   [8][8][128]@ 16384  (32KB)  G2 partials
//   hp_x [8][8][128]@ 24576  (32KB)  G1x partials, then G1a-accumulated preacts
//   a_s  [8][128]   @ 32768  ( 4KB)
//   x2   [2][8][128]@ 33792  ( 8KB)  double-buffered x
//   h_s  [8][128]   @ 35840  ( 4KB)
#define SMEM_FLOATS 36864    // 147456 B

static __device__ __forceinline__ float4 f4add(float4 a, float4 b) {
    return make_float4(a.x + b.x, a.y + b.y, a.z + b.z, a.w + b.w);
}

// tanh(x) = 1 - 2/(e^{2x}+1) via ex2.approx/rcp.approx. Abs err ~1e-7,
// saturates correctly at +-inf.
static __device__ __forceinline__ float tanh_fast(float v) {
    float e, r;
    asm("ex2.approx.f32 %0, %1;" : "=f"(e) : "f"(v * 2.8853900817779268f));
    asm("rcp.approx.f32 %0, %1;" : "=f"(r) : "f"(e + 1.0f));
    return fmaf(-2.0f, r, 1.0f);
}

// 16-k x 4-row x 4-col GEMM partial with register weights (fresh write).
static __device__ __forceinline__ void gemm16_rows(
    const float* __restrict__ act, const ulonglong2* __restrict__ w,
    float* __restrict__ outp, int rlo)
{
    ulonglong2 acc[4];
    #pragma unroll
    for (int r = 0; r < 4; ++r) { acc[r].x = 0ull; acc[r].y = 0ull; }
    #pragma unroll
    for (int kb = 0; kb < 4; ++kb) {
        float4 av[4];
        #pragma unroll
        for (int r = 0; r < 4; ++r)
            av[r] = *(const float4*)(act + (rlo + r) * 128 + kb * 4);
        #pragma unroll
        for (int kk = 0; kk < 4; ++kk) {
            const ulonglong2 ww = w[kb * 4 + kk];
            #pragma unroll
            for (int r = 0; r < 4; ++r) {
                float s = (kk == 0) ? av[r].x : (kk == 1) ? av[r].y
                        : (kk == 2) ? av[r].z : av[r].w;
                u64 sp; PACK2(sp, s);
                FMA2(acc[r].x, sp, ww.x);
                FMA2(acc[r].y, sp, ww.y);
            }
        }
    }
    #pragma unroll
    for (int r = 0; r < 4; ++r)
        *(ulonglong2*)(outp + (rlo + r) * 128) = acc[r];
}

// Same, accumulating on top of the existing buffer contents (G1x partials).
static __device__ __forceinline__ void gemm16_rows_acc(
    const float* __restrict__ act, const ulonglong2* __restrict__ w,
    float* __restrict__ outp, int rlo)
{
    ulonglong2 acc[4];
    #pragma unroll
    for (int r = 0; r < 4; ++r)
        acc[r] = *(const ulonglong2*)(outp + (rlo + r) * 128);
    #pragma unroll
    for (int kb = 0; kb < 4; ++kb) {
        float4 av[4];
        #pragma unroll
        for (int r = 0; r < 4; ++r)
            av[r] = *(const float4*)(act + (rlo + r) * 128 + kb * 4);
        #pragma unroll
        for (int kk = 0; kk < 4; ++kk) {
            const ulonglong2 ww = w[kb * 4 + kk];
            #pragma unroll
            for (int r = 0; r < 4; ++r) {
                float s = (kk == 0) ? av[r].x : (kk == 1) ? av[r].y
                        : (kk == 2) ? av[r].z : av[r].w;
                u64 sp; PACK2(sp, s);
                FMA2(acc[r].x, sp, ww.x);
                FMA2(acc[r].y, sp, ww.y);
            }
        }
    }
    #pragma unroll
    for (int r = 0; r < 4; ++r)
        *(ulonglong2*)(outp + (rlo + r) * 128) = acc[r];
}

__global__ void __cluster_dims__(CSZ, 1, 1) __launch_bounds__(NTHREADS, 1)
rnn_kernel(const float* __restrict__ x,  const float* __restrict__ a0,
           const float* __restrict__ W1, const float* __restrict__ b1,
           const float* __restrict__ W2, const float* __restrict__ b2,
           float* __restrict__ out)
{
    extern __shared__ float sm[];
    float* W2s  = sm;
    float* hp   = sm + 16384;
    float* hp_x = sm + 24576;
    float* a_s  = sm + 32768;
    float* x2   = sm + 33792;   // [2][8][128]
    float* h_s  = sm + 35840;

    const int tid   = threadIdx.x;
    const int lane  = tid & 31;
    const int wid   = tid >> 5;
    const int bx    = blockIdx.x;
    const int crank = bx & (CSZ - 1);
    const int gcl   = bx >> 2;
    const int rowbase = gcl * ROWS;
    const int jbase   = crank * 128;
    const int cj      = lane * 4;

    // ---- G1 weights into registers ----
    // w1x: W1 rows [16*wid, 16*wid+16)           (x part, k = 0..127)
    // w1a: W1 rows [128+16*wid, 128+16*wid+16)   (a part, k = 128..255)
    ulonglong2 w1x[16], w1a[16];
    {
        const float* ws = W1 + (size_t)(16 * wid) * DHID + jbase + cj;
        #pragma unroll
        for (int r = 0; r < 16; ++r)
            w1x[r] = *(const ulonglong2*)(ws + (size_t)r * DHID);
        const float* wa = W1 + (size_t)(128 + 16 * wid) * DHID + jbase + cj;
        #pragma unroll
        for (int r = 0; r < 16; ++r)
            w1a[r] = *(const ulonglong2*)(wa + (size_t)r * DHID);
    }

    // ---- prologue: W2 slice, a0, x(0)->x2[0], x(1)->x2[1], xr=x(2) ----
    for (int i = tid; i < 4096; i += NTHREADS)
        ((float4*)W2s)[i] = ((const float4*)(W2 + (size_t)jbase * DST))[i];
    for (int i = tid; i < 256; i += NTHREADS)
        ((float4*)a_s)[i] = ((const float4*)(a0 + (size_t)rowbase * DST))[i];
    for (int i = tid; i < 256; i += NTHREADS) {
        int r = i >> 5, c4 = (i & 31) << 2;
        *(float4*)(x2 + r * 128 + c4) =
            *(const float4*)(x + (size_t)(rowbase + r) * (size_t)(T_STEPS * DIN) + c4);
    }

    const int crow = wid;                 // this warp's batch row
    const float4 rb1 = *(const float4*)(b1 + jbase + cj);
    const float4 rb2 = *(const float4*)(b2 + cj);

    const float* xrow = x + (size_t)(rowbase + crow) * (size_t)(T_STEPS * DIN) + cj;
    *(float4*)(x2 + 1024 + crow * 128 + cj) = *(const float4*)(xrow + DIN);  // x(1)
    float4 xr = *(const float4*)(xrow + 2 * DIN);                            // x(2)

    const float* g2_wr = W2s + (wid * 16) * 128 + cj;
    float* hpo  = hp   + wid * 1024 + cj;
    float* hpxo = hp_x + wid * 1024 + cj;

    __syncthreads();

    // ---- G1x for step 0 ----
    gemm16_rows(x2 + wid * 16, w1x, hpxo, 0);
    gemm16_rows(x2 + wid * 16, w1x, hpxo, 4);
    __syncthreads();   // B1 (step 0 entry)

    for (int t = 0; t < T_STEPS; ++t) {
        // ---- G1a: accumulate a-part on top of G1x partials in hp_x ----
        gemm16_rows_acc(a_s + wid * 16, w1a, hpxo, 0);
        gemm16_rows_acc(a_s + wid * 16, w1a, hpxo, 4);
        __syncthreads();   // B2

        // ---- C1: preact = sum(8 hp_x bufs) + b1 -> tanh_fast -> h_s ----
        {
            const float* hbx = hp_x + crow * 128 + cj;
            float4 s = *(const float4*)(hbx);
            #pragma unroll
            for (int q = 1; q < 8; ++q)
                s = f4add(s, *(const float4*)(hbx + q * 1024));
            float4 hv;
            hv.x = tanh_fast(s.x + rb1.x);
            hv.y = tanh_fast(s.y + rb1.y);
            hv.z = tanh_fast(s.z + rb1.z);
            hv.w = tanh_fast(s.w + rb1.w);
            *(float4*)(h_s + crow * 128 + cj) = hv;
        }
        __syncthreads();   // B3

        // ---- G2: warp = 16-j chunk x 8 rows, smem weights ----
        {
            ulonglong2 acc[ROWS];
            #pragma unroll
            for (int r = 0; r < ROWS; ++r) { acc[r].x = 0ull; acc[r].y = 0ull; }
            const float* act2 = h_s + wid * 16;
            #pragma unroll
            for (int kb = 0; kb < 4; ++kb) {
                #pragma unroll
                for (int half = 0; half < 2; ++half) {
                    float4 av[4];
                    #pragma unroll
                    for (int r = 0; r < 4; ++r)
                        av[r] = *(const float4*)(act2 + (half * 4 + r) * 128 + kb * 4);
                    const float* wk = g2_wr + kb * 4 * 128;
                    #pragma unroll
                    for (int kk = 0; kk < 4; ++kk) {
                        const ulonglong2 ww = *(const ulonglong2*)(wk + kk * 128);
                        #pragma unroll
                        for (int r = 0; r < 4; ++r) {
                            float s = (kk == 0) ? av[r].x : (kk == 1) ? av[r].y
                                    : (kk == 2) ? av[r].z : av[r].w;
                            u64 sp; PACK2(sp, s);
                            FMA2(acc[half * 4 + r].x, sp, ww.x);
                            FMA2(acc[half * 4 + r].y, sp, ww.y);
                        }
                    }
                }
            }
            #pragma unroll
            for (int r = 0; r < ROWS; ++r)
                *(ulonglong2*)(hpo + r * 128) = acc[r];
        }
        __syncthreads();   // B4

        // ---- C2: combine 8 G2 bufs -> publish my rank's state partial ----
        {
            const float* hb = hp + crow * 128 + cj;
            float4 s = *(const float4*)(hb);
            #pragma unroll
            for (int q = 1; q < 8; ++q)
                s = f4add(s, *(const float4*)(hb + q * 1024));
            __stcg((float4*)&g_pstate[t & 1][gcl][crank][crow][cj], s);
        }
        asm volatile("barrier.cluster.arrive.aligned;" ::: "memory");

        // ---- G1x(t+1) part A: rows 0-3, hides the barrier settle ----
        const float* xb = x2 + ((t + 1) & 1) * 1024 + wid * 16;
        if (t + 1 < T_STEPS)
            gemm16_rows(xb, w1x, hpxo, 0);

        asm volatile("barrier.cluster.wait.aligned;" ::: "memory");

        // ---- fold loads (valid after wait), hidden under G1x part B ----
        float4 p0 = __ldcg((const float4*)&g_pstate[t & 1][gcl][0][crow][cj]);
        float4 p1 = __ldcg((const float4*)&g_pstate[t & 1][gcl][1][crow][cj]);
        float4 p2 = __ldcg((const float4*)&g_pstate[t & 1][gcl][2][crow][cj]);
        float4 p3 = __ldcg((const float4*)&g_pstate[t & 1][gcl][3][crow][cj]);

        if (t + 1 < T_STEPS)
            gemm16_rows(xb, w1x, hpxo, 4);

        // ---- fold combine: a(t+1) = a(t) + sum(partials) + b2 ----
        {
            float4 acc = f4add(f4add(p0, p1), f4add(p2, p3));
            float4 av = *(float4*)(a_s + crow * DST + cj);
            av.x += acc.x + rb2.x;  av.y += acc.y + rb2.y;
            av.z += acc.z + rb2.z;  av.w += acc.w + rb2.w;
            *(float4*)(a_s + crow * DST + cj) = av;
        }
        // ---- stage x(t+2); prefetch x(t+3) ----
        if (t + 2 < T_STEPS) {
            *(float4*)(x2 + (t & 1) * 1024 + crow * 128 + cj) = xr;
            if (t + 3 < T_STEPS)
                xr = *(const float4*)(xrow + (size_t)(t + 3) * DIN);
        }
        __syncthreads();   // B1
    }

    // ---- epilogue: a_s holds a(T); rank 0 writes out ----
    if (crank == 0) {
        float4 av = *(float4*)(a_s + crow * DST + cj);
        *(float4*)(out + (size_t)(rowbase + crow) * DST + cj) = av;
    }
}

extern "C" void kernel_launch(void* const* d_in, const int* in_sizes, int n_in,
                              void* d_out, int out_size) {
    const float* x  = (const float*)d_in[0];
    const float* a0 = (const float*)d_in[1];
    const float* W1 = (const float*)d_in[2];
    const float* b1 = (const float*)d_in[3];
    const float* W2 = (const float*)d_in[4];
    const float* b2 = (const float*)d_in[5];
    float* out = (float*)d_out;

    const size_t smem = SMEM_FLOATS * sizeof(float);   // 147456 B
    cudaFuncSetAttribute(rnn_kernel, cudaFuncAttributeMaxDynamicSharedMemorySize,
                         (int)smem);
    rnn_kernel<<<NCL * CSZ, NTHREADS, smem>>>(x, a0, W1, b1, W2, b2, out);
}